// round 9
// baseline (speedup 1.0000x reference)
#include <cuda_runtime.h>
#include <cstdint>

#define Bsz 2048
#define Tlen 512
#define Ktag 32
#define FULLMASK 0xFFFFFFFFu
#define STRIDE (Bsz * Ktag)

// Per-step alpha rows (exact), recomputed-argmax backtrace reads these.
__device__ float g_alpha[(size_t)Tlen * Bsz * Ktag];   // 134 MB
__device__ int   g_perm[Bsz];                          // length-sorted batch order

union f2u { float2 f; unsigned long long u; };

__device__ __forceinline__ unsigned long long add2(unsigned long long a, unsigned long long b) {
    unsigned long long r; asm("add.rn.f32x2 %0,%1,%2;" : "=l"(r) : "l"(a), "l"(b)); return r;
}
__device__ __forceinline__ unsigned long long pfma2(unsigned long long a, unsigned long long b, unsigned long long c) {
    unsigned long long r; asm("fma.rn.f32x2 %0,%1,%2,%3;" : "=l"(r) : "l"(a), "l"(b), "l"(c)); return r;
}
// order-preserving float->uint bijection (no NaNs in this problem)
__device__ __forceinline__ unsigned ordf(float s) {
    int b = __float_as_int(s);
    return (unsigned)(b ^ ((b >> 31) | 0x80000000));
}
// compiler-only ordering fence (warp converged; smem in-order per warp)
__device__ __forceinline__ void cfence() { asm volatile("" ::: "memory"); }

// ---------------------------------------------------------------------------
// Kernel 0: counting sort by length -> g_perm. One block, 1024 threads.
// ---------------------------------------------------------------------------
__global__ void crf_sort(const int* __restrict__ slen)
{
    __shared__ int hist[512];
    __shared__ int wsum[16];
    const int tid  = threadIdx.x;
    const int lane = tid & 31, wid = tid >> 5;

    for (int i = tid; i < 512; i += 1024) hist[i] = 0;
    __syncthreads();
    for (int b = tid; b < Bsz; b += 1024) atomicAdd(&hist[slen[b] - 1], 1);
    __syncthreads();

    int v = 0, s = 0;
    if (tid < 512) {
        v = hist[tid];
        s = v;
#pragma unroll
        for (int off = 1; off < 32; off <<= 1) {
            int u = __shfl_up_sync(FULLMASK, s, off);
            if (lane >= off) s += u;
        }
        if (lane == 31) wsum[wid] = s;
    }
    __syncthreads();
    if (tid < 16) {
        int t = wsum[tid], ss = t;
#pragma unroll
        for (int off = 1; off < 16; off <<= 1) {
            int u = __shfl_up_sync(0xFFFFu, ss, off);
            if (tid >= off) ss += u;
        }
        wsum[tid] = ss - t;
    }
    __syncthreads();
    if (tid < 512) hist[tid] = (s - v) + wsum[wid];
    __syncthreads();
    for (int b = tid; b < Bsz; b += 1024) {
        int pos = atomicAdd(&hist[slen[b] - 1], 1);
        g_perm[pos] = b;
    }
}

// ---------------------------------------------------------------------------
// Kernel 1: one warp per block, TWO sequences per warp (SIMD lane-split).
// Lanes 0-15 = seq A, lanes 16-31 = seq B; lane (h,q) owns tags {2q, 2q+1}.
// Adjacent-sorted pairing (perm[2w], perm[2w+1]) keeps |LA-LB| small.
// Blocks [0,1024): Viterbi forward + backtrace. Blocks [1024,2048): lse+score.
// ---------------------------------------------------------------------------
__global__ __launch_bounds__(32)
void crf_main(const float* __restrict__ pot,
              const float* __restrict__ trans,
              const int*   __restrict__ slen,
              const int*   __restrict__ tg_in,
              float*       __restrict__ out)
{
    // [parity][ half A at +0 .. 63, half B at +68 (272B) -> disjoint banks ]
    __shared__ __align__(16) float bufD[2][136];
    __shared__ float transS[32 * 33];
    const int w = blockIdx.x;
    const int j = threadIdx.x;
    const int h = j >> 4, q = j & 15;
    const int hoff = h * 68;

    if (w < Bsz / 2) {
        // ============================ VITERBI ============================
        f2u Tp[32];                     // Tp[i] = (T[i][2q], T[i][2q+1])
#pragma unroll
        for (int i = 0; i < 32; ++i)
            Tp[i].f = *(const float2*)&trans[i * 32 + 2 * q];
        for (int i = j; i < 32 * 32; i += 32)
            transS[(i >> 5) * 33 + (i & 31)] = __ldg(&trans[i]);
        __syncwarp();

        const int bA = g_perm[2 * w], bB = g_perm[2 * w + 1];
        const int LA = slen[bA],      LB = slen[bB];
        const int bH = h ? bB : bA;
        const int LH = h ? LB : LA;
        const int Lmax = max(LA, LB);
        const float* pH  = pot + (size_t)bH * Tlen * Ktag + 2 * q;
        float*       aSh = g_alpha + (size_t)bH * Ktag + 2 * q;

        float2 al = *(const float2*)pH;              // t = 0

        auto LD = [&](int t) -> float2 {             // clamped prefetch
            return *(const float2*)(pH + (size_t)min(t, LH - 1) * Ktag);
        };
        auto step = [&](float2 pcv, int t) {
            const int par = t & 1;
            ((float4*)(bufD[par] + hoff))[q] = make_float4(al.x, al.x, al.y, al.y);
            if (t < LH)
                *(float2*)(aSh + (size_t)(t - 1) * STRIDE) = al;
            cfence();
            const ulonglong2* Au = (const ulonglong2*)(bufD[par] + hoff);
            float c0[4], c1[4];
#pragma unroll
            for (int k = 0; k < 4; ++k) { c0[k] = -3.4e38f; c1[k] = -3.4e38f; }
#pragma unroll
            for (int g = 0; g < 16; ++g) {
                const ulonglong2 v = Au[g];          // dup(a_{2g}), dup(a_{2g+1})
                f2u s0, s1;
                s0.u = add2(v.x, Tp[2 * g].u);       // (->out0, ->out1)
                s1.u = add2(v.y, Tp[2 * g + 1].u);
                c0[g & 3] = fmaxf(fmaxf(c0[g & 3], s0.f.x), s1.f.x);
                c1[g & 3] = fmaxf(fmaxf(c1[g & 3], s0.f.y), s1.f.y);
            }
            const float n0 = pcv.x + fmaxf(fmaxf(c0[0], c0[1]), fmaxf(c0[2], c0[3]));
            const float n1 = pcv.y + fmaxf(fmaxf(c1[0], c1[1]), fmaxf(c1[2], c1[3]));
            if (t < LH) { al.x = n0; al.y = n1; }    // freeze shorter seq
        };

        float2 r0 = LD(1), r1 = LD(2), r2 = LD(3), r3 = LD(4),
               r4 = LD(5), r5 = LD(6), r6 = LD(7), r7 = LD(8);
        int t = 1;
#pragma unroll 1
        for (; t + 8 <= Lmax; t += 8) {
            step(r0, t + 0); r0 = LD(t + 8);
            step(r1, t + 1); r1 = LD(t + 9);
            step(r2, t + 2); r2 = LD(t + 10);
            step(r3, t + 3); r3 = LD(t + 11);
            step(r4, t + 4); r4 = LD(t + 12);
            step(r5, t + 5); r5 = LD(t + 13);
            step(r6, t + 6); r6 = LD(t + 14);
            step(r7, t + 7); r7 = LD(t + 15);
        }
#pragma unroll 1
        for (; t < Lmax; ++t) step(LD(t), t);

        // publish final alphas (plain layout: half h -> 32 floats at h*68)
        ((float2*)(bufD[0] + hoff))[q] = al;
        __syncwarp();
        __threadfence_block();                       // g_alpha visible cross-lane

        // -------- per-task epilogue: argmax, tags, backtrace --------
#pragma unroll 1
        for (int task = 0; task < 2; ++task) {
            const int b = task ? bB : bA;
            const int L = task ? LB : LA;
            const float alphaF = bufD[0][task * 68 + j];
            float* aSt = g_alpha + (size_t)b * Ktag + j;

            const unsigned ua = ordf(alphaF);
            const unsigned um = __reduce_max_sync(FULLMASK, ua);
            const int idx = __ffs((int)__ballot_sync(FULLMASK, ua == um)) - 1;
            const float v = __shfl_sync(FULLMASK, alphaF, idx);
            if (j == 0) out[(size_t)Bsz * Tlen + b] = v;     // best_score

            float* tagOut = out + (size_t)b * Tlen;
            for (int tt = L - 1 + j; tt < Tlen; tt += 32)
                tagOut[tt] = (float)idx;                     // tail = last tag

            if (L >= 2) {
                int tag = idx;
                float myTag = 0.f;
                float cur[8], nxt[8];
                const int t0 = L - 1;
#pragma unroll
                for (int k = 0; k < 8; ++k) {
                    const int tt = t0 - k;
                    cur[k] = (tt >= 1) ? aSt[(size_t)(tt - 1) * STRIDE] : 0.f;
                }
#pragma unroll 1
                for (int tc = t0; tc >= 1; tc -= 8) {
#pragma unroll
                    for (int k = 0; k < 8; ++k) {            // prefetch next chunk
                        const int tt = tc - 8 - k;
                        nxt[k] = (tt >= 1) ? aSt[(size_t)(tt - 1) * STRIDE] : 0.f;
                    }
#pragma unroll
                    for (int k = 0; k < 8; ++k) {
                        const int tt = tc - k;
                        if (tt >= 1) {
                            const float s = cur[k] + transS[j * 33 + tag];
                            const unsigned u = ordf(s);
                            const unsigned mm = __reduce_max_sync(FULLMASK, u);
                            const int prev = __ffs((int)__ballot_sync(FULLMASK, u == mm)) - 1;
                            const int pos = tt - 1;
                            if ((pos & 31) == j) myTag = (float)prev;
                            if ((pos & 31) == 0 && pos + j <= L - 2)
                                tagOut[pos + j] = myTag;     // coalesced flush
                            tag = prev;
                        }
                    }
#pragma unroll
                    for (int k = 0; k < 8; ++k) cur[k] = nxt[k];
                }
            }
        }
    } else {
        // ========================== LOGSUMEXP + SCORE ==========================
        const int w2 = w - Bsz / 2;
        f2u Ep[32];                     // Ep[i] = (e^T[i][2q], e^T[i][2q+1])
#pragma unroll
        for (int i = 0; i < 32; ++i) {
            const float2 tv = *(const float2*)&trans[i * 32 + 2 * q];
            Ep[i].f.x = expf(tv.x);
            Ep[i].f.y = expf(tv.y);
        }

        const int bA = g_perm[2 * w2], bB = g_perm[2 * w2 + 1];
        const int LA = slen[bA],       LB = slen[bB];
        const int bH = h ? bB : bA;
        const int LH = h ? LB : LA;
        const int Lmax = max(LA, LB);
        const int msrc = j & 16;                     // lane holding own seq's tag0
        const float* pH = pot + (size_t)bH * Tlen * Ktag + 2 * q;

        float2 al = *(const float2*)pH;

        auto LD = [&](int t) -> float2 {
            return *(const float2*)(pH + (size_t)min(t, LH - 1) * Ktag);
        };
        auto step = [&](float2 pcv, int t) {
            const int par = t & 1;
            // shift by own seq's tag-0 alpha (spread bounded, fp32-safe)
            const float m  = __shfl_sync(FULLMASK, al.x, msrc);
            const float e0 = __expf(al.x - m);
            const float e1 = __expf(al.y - m);
            ((float4*)(bufD[par] + hoff))[q] = make_float4(e0, e0, e1, e1);
            cfence();
            const ulonglong2* Au = (const ulonglong2*)(bufD[par] + hoff);
            f2u a0[4], a1[4];
#pragma unroll
            for (int k = 0; k < 4; ++k) { a0[k].u = 0ull; a1[k].u = 0ull; }
#pragma unroll
            for (int g = 0; g < 16; ++g) {
                const ulonglong2 v = Au[g];
                a0[g & 3].u = pfma2(v.x, Ep[2 * g].u,     a0[g & 3].u);
                a1[g & 3].u = pfma2(v.y, Ep[2 * g + 1].u, a1[g & 3].u);
            }
            f2u S;
            S.u = add2(add2(add2(a0[0].u, a0[1].u), add2(a0[2].u, a0[3].u)),
                       add2(add2(a1[0].u, a1[1].u), add2(a1[2].u, a1[3].u)));
            const float n0 = pcv.x + m + __logf(S.f.x);
            const float n1 = pcv.y + m + __logf(S.f.y);
            if (t < LH) { al.x = n0; al.y = n1; }
        };

        float2 r0 = LD(1), r1 = LD(2), r2 = LD(3), r3 = LD(4),
               r4 = LD(5), r5 = LD(6), r6 = LD(7), r7 = LD(8);
        int t = 1;
#pragma unroll 1
        for (; t + 8 <= Lmax; t += 8) {
            step(r0, t + 0); r0 = LD(t + 8);
            step(r1, t + 1); r1 = LD(t + 9);
            step(r2, t + 2); r2 = LD(t + 10);
            step(r3, t + 3); r3 = LD(t + 11);
            step(r4, t + 4); r4 = LD(t + 12);
            step(r5, t + 5); r5 = LD(t + 13);
            step(r6, t + 6); r6 = LD(t + 14);
            step(r7, t + 7); r7 = LD(t + 15);
        }
#pragma unroll 1
        for (; t < Lmax; ++t) step(LD(t), t);

        ((float2*)(bufD[0] + hoff))[q] = al;
        __syncwarp();

        // -------- per-task epilogue: logNorm, sequence score, loglik --------
#pragma unroll 1
        for (int task = 0; task < 2; ++task) {
            const int b = task ? bB : bA;
            const int L = task ? LB : LA;
            const float alphaF = bufD[0][task * 68 + j];

            float mm = alphaF;
#pragma unroll
            for (int off = 16; off; off >>= 1)
                mm = fmaxf(mm, __shfl_xor_sync(FULLMASK, mm, off));
            float e = __expf(alphaF - mm);
#pragma unroll
            for (int off = 16; off; off >>= 1)
                e += __shfl_xor_sync(FULLMASK, e, off);
            const float logNorm = mm + __logf(e);

            const int*   tg = tg_in + (size_t)b * Tlen;
            const float* p0 = pot + (size_t)b * Tlen * Ktag;
            float s = 0.f;
            for (int t2 = j; t2 < L; t2 += 32) {
                const int tt = tg[t2];
                s += __ldg(&p0[t2 * Ktag + tt]);
                if (t2 < L - 1) s += __ldg(&trans[tt * 32 + tg[t2 + 1]]);
            }
#pragma unroll
            for (int off = 16; off; off >>= 1)
                s += __shfl_xor_sync(FULLMASK, s, off);
            if (j == 0)
                out[(size_t)Bsz * Tlen + Bsz + b] = s - logNorm;
        }
    }
}

// ---------------------------------------------------------------------------
extern "C" void kernel_launch(void* const* d_in, const int* in_sizes, int n_in,
                              void* d_out, int out_size)
{
    const float* pot   = (const float*)d_in[0];
    const float* trans = (const float*)d_in[1];
    const int*   slen  = (const int*)d_in[2];
    const int*   tags  = (const int*)d_in[3];
    float*       out   = (float*)d_out;

    crf_sort<<<1, 1024>>>(slen);
    crf_main<<<Bsz, 32>>>(pot, trans, slen, tags, out);
}

// round 11
// speedup vs baseline: 1.2190x; 1.2190x over previous
#include <cuda_runtime.h>
#include <cstdint>

#define Bsz 2048
#define Tlen 512
#define Ktag 32
#define FULLMASK 0xFFFFFFFFu
#define STRIDE (Bsz * Ktag)

// Per-step alpha rows (exact); recomputed-argmax backtrace reads these.
__device__ float g_alpha[(size_t)Tlen * Bsz * Ktag];   // 134 MB

union f2u { float2 f; unsigned long long u; };

__device__ __forceinline__ unsigned long long add2(unsigned long long a, unsigned long long b) {
    unsigned long long r; asm("add.rn.f32x2 %0,%1,%2;" : "=l"(r) : "l"(a), "l"(b)); return r;
}
__device__ __forceinline__ unsigned long long pfma2(unsigned long long a, unsigned long long b, unsigned long long c) {
    unsigned long long r; asm("fma.rn.f32x2 %0,%1,%2,%3;" : "=l"(r) : "l"(a), "l"(b), "l"(c)); return r;
}
// order-preserving float->uint bijection (no NaNs in this problem)
__device__ __forceinline__ unsigned ordf(float s) {
    int b = __float_as_int(s);
    return (unsigned)(b ^ ((b >> 31) | 0x80000000));
}
// compiler-only ordering fence (warp converged; smem in-order per warp)
__device__ __forceinline__ void cfence() { asm volatile("" ::: "memory"); }

// ---------------------------------------------------------------------------
// One warp per block, ONE task per warp.
// Blocks [0, 2048):    Viterbi forward + backtrace + tags + best_score.
// Blocks [2048, 4096): logsumexp forward + sequence score + loglik.
// Lane j owns tag column j. Potentials prefetched 8 deep (DRAM ~577cyc).
// ---------------------------------------------------------------------------
__global__ __launch_bounds__(32, 28)
void crf_main(const float* __restrict__ pot,
              const float* __restrict__ trans,
              const int*   __restrict__ slen,
              const int*   __restrict__ tg_in,
              float*       __restrict__ out)
{
    __shared__ __align__(16) float buf[2][32];
    __shared__ float transS[32 * 33];               // [i][tag], pad 33
    const int w = blockIdx.x;
    const int j = threadIdx.x;

    if (w < Bsz) {
        // ============================ VITERBI ============================
        const int b = w;
        f2u Tp[16];                                  // packed rows (2q,2q+1), col j
#pragma unroll
        for (int q = 0; q < 16; ++q) {
            Tp[q].f.x = __ldg(&trans[(2 * q) * 32 + j]);
            Tp[q].f.y = __ldg(&trans[(2 * q + 1) * 32 + j]);
        }
        for (int q = j; q < 32 * 32; q += 32)       // transS[i*33+c] = T[i][c]
            transS[(q >> 5) * 33 + (q & 31)] = __ldg(&trans[q]);
        __syncwarp();

        const int L = slen[b];
        const float* p = pot + (size_t)b * Tlen * Ktag + j;
        float* aSt = g_alpha + (size_t)b * Ktag + j;

        float alpha = __ldg(p);                      // t = 0

        auto LD = [&](int t) -> float {              // clamped prefetch load
            return __ldg(p + (size_t)min(t, L - 1) * Ktag);
        };
        auto step = [&](float pcv, int t) {
            buf[t & 1][j] = alpha;
            aSt[(size_t)(t - 1) * STRIDE] = alpha;   // save for backtrace
            cfence();                                // converged-warp broadcast
            const ulonglong2* A = (const ulonglong2*)buf[t & 1];
            float m0 = -3.4e38f, m1 = -3.4e38f, m2 = -3.4e38f, m3 = -3.4e38f;
#pragma unroll
            for (int g = 0; g < 8; ++g) {
                const ulonglong2 av = A[g];
                f2u s0, s1;
                s0.u = add2(av.x, Tp[2 * g].u);
                s1.u = add2(av.y, Tp[2 * g + 1].u);
                m0 = fmaxf(m0, s0.f.x); m1 = fmaxf(m1, s0.f.y);
                m2 = fmaxf(m2, s1.f.x); m3 = fmaxf(m3, s1.f.y);
            }
            alpha = pcv + fmaxf(fmaxf(m0, m1), fmaxf(m2, m3));
        };

        float q0 = LD(1), q1 = LD(2), q2 = LD(3), q3 = LD(4),
              q4 = LD(5), q5 = LD(6), q6 = LD(7), q7 = LD(8);
        int t = 1;
#pragma unroll 1
        for (; t + 8 <= L; t += 8) {
            step(q0, t + 0); q0 = LD(t + 8);
            step(q1, t + 1); q1 = LD(t + 9);
            step(q2, t + 2); q2 = LD(t + 10);
            step(q3, t + 3); q3 = LD(t + 11);
            step(q4, t + 4); q4 = LD(t + 12);
            step(q5, t + 5); q5 = LD(t + 13);
            step(q6, t + 6); q6 = LD(t + 14);
            step(q7, t + 7); q7 = LD(t + 15);
        }
#pragma unroll 1
        for (; t < L; ++t) step(__ldg(p + (size_t)t * Ktag), t);

        // final max/argmax (first-max) via redux + ballot
        const unsigned ua = ordf(alpha);
        const unsigned um = __reduce_max_sync(FULLMASK, ua);
        const int idx = __ffs((int)__ballot_sync(FULLMASK, ua == um)) - 1;
        const float v = __shfl_sync(FULLMASK, alpha, idx);
        if (j == 0) out[(size_t)Bsz * Tlen + b] = v;     // best_score

        float* tagOut = out + (size_t)b * Tlen;
        for (int tt = L - 1 + j; tt < Tlen; tt += 32)
            tagOut[tt] = (float)idx;                     // tail = last tag

        // ---------- backtrace: recompute argmax from stored alphas ----------
        if (L >= 2) {
            int tag = idx;
            float myTag = 0.f;
            float cur[8], nxt[8];
            const int t0 = L - 1;
#pragma unroll
            for (int k = 0; k < 8; ++k) {
                const int tt = t0 - k;
                cur[k] = (tt >= 1) ? aSt[(size_t)(tt - 1) * STRIDE] : 0.f;
            }
#pragma unroll 1
            for (int tc = t0; tc >= 1; tc -= 8) {
#pragma unroll
                for (int k = 0; k < 8; ++k) {            // prefetch next chunk
                    const int tt = tc - 8 - k;
                    nxt[k] = (tt >= 1) ? aSt[(size_t)(tt - 1) * STRIDE] : 0.f;
                }
#pragma unroll
                for (int k = 0; k < 8; ++k) {
                    const int tt = tc - k;
                    if (tt >= 1) {
                        const float s = cur[k] + transS[j * 33 + tag];
                        const unsigned u = ordf(s);
                        const unsigned mm = __reduce_max_sync(FULLMASK, u);
                        const int prev = __ffs((int)__ballot_sync(FULLMASK, u == mm)) - 1;
                        const int pos = tt - 1;
                        if ((pos & 31) == j) myTag = (float)prev;
                        if ((pos & 31) == 0 && pos + j <= L - 2)
                            tagOut[pos + j] = myTag;     // coalesced flush
                        tag = prev;
                    }
                }
#pragma unroll
                for (int k = 0; k < 8; ++k) cur[k] = nxt[k];
            }
        }
    } else {
        // ========================== LOGSUMEXP + SCORE ==========================
        const int b = w - Bsz;
        f2u Ep[16];
#pragma unroll
        for (int q = 0; q < 16; ++q) {
            Ep[q].f.x = expf(__ldg(&trans[(2 * q) * 32 + j]));
            Ep[q].f.y = expf(__ldg(&trans[(2 * q + 1) * 32 + j]));
        }

        const int L = slen[b];
        const float* p = pot + (size_t)b * Tlen * Ktag + j;

        float alpha = __ldg(p);

        auto LD = [&](int t) -> float {
            return __ldg(p + (size_t)min(t, L - 1) * Ktag);
        };
        auto step = [&](float pcv, int t) {
            // shift by lane0 alpha: intra-step spread bounded, fp32-safe
            const float m = __shfl_sync(FULLMASK, alpha, 0);
            const float e = __expf(alpha - m);
            buf[t & 1][j] = e;
            cfence();                                // converged-warp broadcast
            const ulonglong2* A = (const ulonglong2*)buf[t & 1];
            f2u a0, a1, a2, a3;
            a0.u = 0ull; a1.u = 0ull; a2.u = 0ull; a3.u = 0ull;
#pragma unroll
            for (int g = 0; g < 8; g += 2) {         // 4 packed accs, 4 deep
                const ulonglong2 av0 = A[g];
                const ulonglong2 av1 = A[g + 1];
                a0.u = pfma2(av0.x, Ep[2 * g].u,     a0.u);
                a1.u = pfma2(av0.y, Ep[2 * g + 1].u, a1.u);
                a2.u = pfma2(av1.x, Ep[2 * g + 2].u, a2.u);
                a3.u = pfma2(av1.y, Ep[2 * g + 3].u, a3.u);
            }
            a0.u = add2(a0.u, a1.u);
            a2.u = add2(a2.u, a3.u);
            a0.u = add2(a0.u, a2.u);
            alpha = pcv + m + __logf(a0.f.x + a0.f.y);
        };

        float q0 = LD(1), q1 = LD(2), q2 = LD(3), q3 = LD(4),
              q4 = LD(5), q5 = LD(6), q6 = LD(7), q7 = LD(8);
        int t = 1;
#pragma unroll 1
        for (; t + 8 <= L; t += 8) {
            step(q0, t + 0); q0 = LD(t + 8);
            step(q1, t + 1); q1 = LD(t + 9);
            step(q2, t + 2); q2 = LD(t + 10);
            step(q3, t + 3); q3 = LD(t + 11);
            step(q4, t + 4); q4 = LD(t + 12);
            step(q5, t + 5); q5 = LD(t + 13);
            step(q6, t + 6); q6 = LD(t + 14);
            step(q7, t + 7); q7 = LD(t + 15);
        }
#pragma unroll 1
        for (; t < L; ++t) step(__ldg(p + (size_t)t * Ktag), t);

        // final logsumexp over lanes
        float mm = alpha;
#pragma unroll
        for (int off = 16; off; off >>= 1)
            mm = fmaxf(mm, __shfl_xor_sync(FULLMASK, mm, off));
        float e = __expf(alpha - mm);
#pragma unroll
        for (int off = 16; off; off >>= 1)
            e += __shfl_xor_sync(FULLMASK, e, off);
        const float logNorm = mm + __logf(e);

        // sequence score + log-likelihood
        const int*   tg = tg_in + (size_t)b * Tlen;
        const float* p0 = pot + (size_t)b * Tlen * Ktag;
        float s = 0.f;
        for (int t2 = j; t2 < L; t2 += 32) {
            const int tt = tg[t2];
            s += __ldg(&p0[t2 * Ktag + tt]);
            if (t2 < L - 1) s += __ldg(&trans[tt * 32 + tg[t2 + 1]]);
        }
#pragma unroll
        for (int off = 16; off; off >>= 1)
            s += __shfl_xor_sync(FULLMASK, s, off);
        if (j == 0)
            out[(size_t)Bsz * Tlen + Bsz + b] = s - logNorm;
    }
}

// ---------------------------------------------------------------------------
extern "C" void kernel_launch(void* const* d_in, const int* in_sizes, int n_in,
                              void* d_out, int out_size)
{
    const float* pot   = (const float*)d_in[0];
    const float* trans = (const float*)d_in[1];
    const int*   slen  = (const int*)d_in[2];
    const int*   tags  = (const int*)d_in[3];
    float*       out   = (float*)d_out;

    crf_main<<<2 * Bsz, 32>>>(pot, trans, slen, tags, out);
}